// round 12
// baseline (speedup 1.0000x reference)
#include <cuda_runtime.h>
#include <math.h>
#include <stdint.h>

#define B_SZ    4
#define SEQ_L   2048
#define D_MODEL 1024
#define D_INNER 2048
#define D_STATE 16
#define DT_RANK 64
#define IN_DIM  4192
#define NROWS   (B_SZ*SEQ_L)     /* 8192 */
#define NC1     2064             /* x_in(2048) + B(16) columns */
#define COL_OFF 2048
#define WR_LD   2176             /* g_wr row stride (floats), cols >=2064 zero */
#define MY_INT_MAX 0x7fffffff

// ---------------- scratch (static device, no allocs) ----------------
__device__ float g_projT[(size_t)NROWS*NC1];            // x_in | B  (row-major, ld=NC1)
__device__ float g_xr[(size_t)NROWS*D_MODEL];           // tf32-rounded x
__device__ float g_wr[(size_t)D_MODEL*WR_LD];           // tf32-rounded W[:,2048:4112], zero-padded
__device__ float g_dtr[NROWS*DT_RANK];
__device__ float g_dt[(size_t)B_SZ*D_INNER*SEQ_L];      // (b,d,t)
__device__ float g_R [(size_t)B_SZ*D_INNER*SEQ_L];      // suffix sums, tail only
__device__ float g_xc[(size_t)B_SZ*D_INNER*SEQ_L];      // silu(conv), tail only
__device__ float g_csum[B_SZ*32*D_INNER];               // per-64-chunk dt sums
__device__ float g_z [B_SZ*D_INNER];
__device__ float g_Cl[B_SZ*D_STATE];
__device__ int   g_tstar[B_SZ*D_INNER];
__device__ int   g_cutraw[B_SZ];
__device__ float g_fm[B_SZ*D_INNER];

__device__ __forceinline__ float softplusf(float x){
    return (x > 15.f) ? x : log1pf(__expf(x));
}

__device__ __forceinline__ float tf32r(float x){
    uint32_t r;
    asm("cvt.rna.tf32.f32 %0, %1;" : "=r"(r) : "f"(x));
    return __uint_as_float(r);
}

__device__ __forceinline__ void mma_tf32(float* c, const uint32_t* a, const uint32_t* b){
    asm volatile(
        "mma.sync.aligned.m16n8k8.row.col.f32.tf32.tf32.f32 "
        "{%0,%1,%2,%3}, {%4,%5,%6,%7}, {%8,%9}, {%0,%1,%2,%3};"
        : "+f"(c[0]), "+f"(c[1]), "+f"(c[2]), "+f"(c[3])
        : "r"(a[0]), "r"(a[1]), "r"(a[2]), "r"(a[3]), "r"(b[0]), "r"(b[1]));
}

__device__ __forceinline__ void cp16(uint32_t dst, const void* src){
    asm volatile("cp.async.cg.shared.global [%0], [%1], 16;" :: "r"(dst), "l"(src));
}
__device__ __forceinline__ void cp_commit(){
    asm volatile("cp.async.commit_group;");
}

// -------- K0: z and C for the LAST timestep only (split-K) --------
__global__ void k_zc(const float* __restrict__ x, const float* __restrict__ W,
                     const float* __restrict__ bias){
    int b = blockIdx.y;
    int tid = threadIdx.x;
    int cl = tid & 63, kq = tid >> 6;
    int c = blockIdx.x*64 + cl;
    __shared__ float xs[1024];
    __shared__ float p[4][64];
    const float* xrow = x + ((size_t)(b*SEQ_L + SEQ_L-1))*D_MODEL;
    for (int i = tid; i < 1024; i += 256) xs[i] = xrow[i];
    __syncthreads();
    float acc = 0.f;
    if (c < 2064){
        int wcol = (c < 2048) ? c : (4112 + (c - 2048));
        const float* wp = W + (size_t)(kq*256)*IN_DIM + wcol;
        #pragma unroll 8
        for (int k = 0; k < 256; k++) acc += xs[kq*256 + k] * wp[(size_t)k*IN_DIM];
    }
    p[kq][cl] = acc;
    __syncthreads();
    if (tid < 64){
        int cc = blockIdx.x*64 + tid;
        if (cc < 2064){
            float s = p[0][tid] + p[1][tid] + p[2][tid] + p[3][tid];
            int wcol = (cc < 2048) ? cc : (4112 + (cc - 2048));
            s += bias[wcol];
            if (cc < 2048) g_z[b*D_INNER + cc] = s;
            else           g_Cl[b*D_STATE + (cc-2048)] = s;
        }
    }
}

// -------- K1: dtr GEMM (blocks 0..255) + tf32 pre-round of x / W slab (256..1791) --------
__global__ void k_dtr(const float* __restrict__ x, const float* __restrict__ W){
    int tid = threadIdx.x;
    if (blockIdx.x >= 256){
        int pid = blockIdx.x - 256;
        if (pid < 1024){
            // x -> g_xr (tf32-rounded). 2,097,152 float4 over 1024 blocks.
            for (size_t i = (size_t)pid*256 + tid; i < 2097152u; i += 262144u){
                float4 v = ((const float4*)x)[i];
                float4 o = make_float4(tf32r(v.x), tf32r(v.y), tf32r(v.z), tf32r(v.w));
                ((float4*)g_xr)[i] = o;
            }
        } else {
            // W[:,2048:4112] -> g_wr [1024][2176] with zero pad. 544 float4 per row.
            int p2 = pid - 1024;   // 0..511
            for (size_t i = (size_t)p2*256 + tid; i < 557056u; i += 131072u){
                int k  = (int)(i / 544);
                int c4 = (int)(i % 544);
                float4 o = make_float4(0.f,0.f,0.f,0.f);
                if (c4 < 516){
                    float4 v = *(const float4*)(W + (size_t)k*IN_DIM + COL_OFF + c4*4);
                    o = make_float4(tf32r(v.x), tf32r(v.y), tf32r(v.z), tf32r(v.w));
                }
                ((float4*)g_wr)[(size_t)k*544 + c4] = o;
            }
        }
        return;
    }
    int r0 = blockIdx.x * 32;
    if (blockIdx.x == 0 && tid < B_SZ) g_cutraw[tid] = MY_INT_MAX;
    __shared__ float xs[32][64];
    __shared__ float ws[64][64];
    int rowq = tid >> 4;
    int cg   = tid & 15;
    float acc0[4] = {0,0,0,0};
    float acc1[4] = {0,0,0,0};
    for (int k0 = 0; k0 < 1024; k0 += 64){
        __syncthreads();
        float4 a0 = *(const float4*)(x + (size_t)(r0+rowq)*1024 + k0 + cg*4);
        float4 a1 = *(const float4*)(x + (size_t)(r0+rowq+16)*1024 + k0 + cg*4);
        *(float4*)&xs[rowq][cg*4]    = a0;
        *(float4*)&xs[rowq+16][cg*4] = a1;
        #pragma unroll
        for (int jj = 0; jj < 4; jj++){
            int k = (tid>>4) + jj*16;
            *(float4*)&ws[k][cg*4] =
                *(const float4*)(W + (size_t)(k0+k)*IN_DIM + 4128 + cg*4);
        }
        __syncthreads();
        #pragma unroll
        for (int k = 0; k < 64; k++){
            float xa = xs[rowq][k], xb = xs[rowq+16][k];
            float4 w = *(float4*)&ws[k][cg*4];
            acc0[0] = fmaf(xa, w.x, acc0[0]); acc0[1] = fmaf(xa, w.y, acc0[1]);
            acc0[2] = fmaf(xa, w.z, acc0[2]); acc0[3] = fmaf(xa, w.w, acc0[3]);
            acc1[0] = fmaf(xb, w.x, acc1[0]); acc1[1] = fmaf(xb, w.y, acc1[1]);
            acc1[2] = fmaf(xb, w.z, acc1[2]); acc1[3] = fmaf(xb, w.w, acc1[3]);
        }
    }
    *(float4*)(g_dtr + (size_t)(r0+rowq)*64 + cg*4)    = make_float4(acc0[0],acc0[1],acc0[2],acc0[3]);
    *(float4*)(g_dtr + (size_t)(r0+rowq+16)*64 + cg*4) = make_float4(acc1[0],acc1[1],acc1[2],acc1[3]);
}

// -------- K2: dt = softplus(dtr @ W2 + b2), transposed (b,d,t) + chunk sums --------
__global__ void k_dt(const float* __restrict__ W2, const float* __restrict__ b2){
    int b = blockIdx.z;
    int chunk = blockIdx.x;
    int t0 = chunk * 64;
    int d0 = blockIdx.y * 64;
    __shared__ float ds[64][65];
    __shared__ float ws[64][64];
    __shared__ float bs[64];
    int tid = threadIdx.x;
    #pragma unroll
    for (int jj = 0; jj < 4; jj++){
        int tt = (tid>>4) + jj*16;
        int kk = (tid & 15)*4;
        float4 v = *(const float4*)(g_dtr + (size_t)(b*SEQ_L + t0 + tt)*64 + kk);
        ds[tt][kk] = v.x; ds[tt][kk+1] = v.y; ds[tt][kk+2] = v.z; ds[tt][kk+3] = v.w;
        int k = (tid>>4) + jj*16;
        *(float4*)&ws[k][kk] = *(const float4*)(W2 + (size_t)k*D_INNER + d0 + kk);
    }
    if (tid < 64) bs[tid] = b2[d0 + tid];
    __syncthreads();
    int tq = tid >> 3;
    int cg = tid & 7;
    float acc0[8], acc1[8];
    #pragma unroll
    for (int j = 0; j < 8; j++){ acc0[j] = bs[cg*8+j]; acc1[j] = acc0[j]; }
    #pragma unroll
    for (int k = 0; k < 64; k++){
        float a0 = ds[tq*2][k], a1 = ds[tq*2+1][k];
        float4 w0 = *(float4*)&ws[k][cg*8];
        float4 w1 = *(float4*)&ws[k][cg*8+4];
        acc0[0]=fmaf(a0,w0.x,acc0[0]); acc0[1]=fmaf(a0,w0.y,acc0[1]);
        acc0[2]=fmaf(a0,w0.z,acc0[2]); acc0[3]=fmaf(a0,w0.w,acc0[3]);
        acc0[4]=fmaf(a0,w1.x,acc0[4]); acc0[5]=fmaf(a0,w1.y,acc0[5]);
        acc0[6]=fmaf(a0,w1.z,acc0[6]); acc0[7]=fmaf(a0,w1.w,acc0[7]);
        acc1[0]=fmaf(a1,w0.x,acc1[0]); acc1[1]=fmaf(a1,w0.y,acc1[1]);
        acc1[2]=fmaf(a1,w0.z,acc1[2]); acc1[3]=fmaf(a1,w0.w,acc1[3]);
        acc1[4]=fmaf(a1,w1.x,acc1[4]); acc1[5]=fmaf(a1,w1.y,acc1[5]);
        acc1[6]=fmaf(a1,w1.z,acc1[6]); acc1[7]=fmaf(a1,w1.w,acc1[7]);
    }
    float sp0[8], sp1[8];
    #pragma unroll
    for (int j = 0; j < 8; j++){
        sp0[j] = softplusf(acc0[j]);
        sp1[j] = softplusf(acc1[j]);
        int d = d0 + cg*8 + j;
        *(float2*)(g_dt + ((size_t)(b*D_INNER + d))*SEQ_L + t0 + tq*2) =
            make_float2(sp0[j], sp1[j]);
    }
    __syncthreads();
    float* pw = &ws[0][0];
    #pragma unroll
    for (int j = 0; j < 8; j++) pw[tq*64 + cg*8 + j] = sp0[j] + sp1[j];
    __syncthreads();
    #pragma unroll
    for (int off = 16; off > 0; off >>= 1){
        if (tq < off){
            #pragma unroll
            for (int j = 0; j < 8; j++)
                pw[tq*64 + cg*8 + j] += pw[(tq+off)*64 + cg*8 + j];
        }
        __syncthreads();
    }
    if (tq == 0){
        #pragma unroll
        for (int j = 0; j < 8; j++)
            g_csum[(b*32 + chunk)*D_INNER + d0 + cg*8 + j] = pw[cg*8 + j];
    }
}

// -------- K3: scan v2 — csum-driven; one warp per (b,d) row --------
__global__ void k_scan(const float* __restrict__ A_log){
    int tid = threadIdx.x;
    int lane = tid & 31;
    int d = blockIdx.x*8 + (tid >> 5);
    int b = blockIdx.y;
    size_t base = ((size_t)(b*D_INNER + d))*SEQ_L;

    float a = (lane < 16) ? -__expf(A_log[d*16 + lane]) : -3.4e38f;
    #pragma unroll
    for (int off = 16; off > 0; off >>= 1)
        a = fmaxf(a, __shfl_xor_sync(0xffffffffu, a, off));
    float Th = -32.f / a;

    float cs = g_csum[(b*32 + lane)*D_INNER + d];
    float S = cs;
    #pragma unroll
    for (int off = 1; off < 32; off <<= 1){
        float v = __shfl_down_sync(0xffffffffu, S, off);
        if (lane + off < 32) S += v;
    }
    float Snext = __shfl_down_sync(0xffffffffu, S, 1);
    if (lane == 31) Snext = 0.f;
    unsigned liveMask = __ballot_sync(0xffffffffu, Snext < Th);
    int cstar = __ffs(liveMask) - 1;

    int tstar = SEQ_L - 1;
    for (int c = cstar; c < 32; c++){
        float Sn = __shfl_sync(0xffffffffu, Snext, c);
        float2 dv = *(const float2*)(g_dt + base + c*64 + lane*2);
        float pair = dv.x + dv.y;
        float P = pair;
        #pragma unroll
        for (int off = 1; off < 32; off <<= 1){
            float v = __shfl_down_sync(0xffffffffu, P, off);
            if (lane + off < 32) P += v;
        }
        float tailp = P - pair;
        float R1 = Sn + tailp;
        float R0 = R1 + dv.y;
        *(float2*)(g_R + base + c*64 + lane*2) = make_float2(R0, R1);
        if (c == cstar){
            unsigned m0 = __ballot_sync(0xffffffffu, R0 < Th);
            unsigned m1 = __ballot_sync(0xffffffffu, R1 < Th);
            int c0 = m0 ? (__ffs(m0)-1)*2     : 0x7fff;
            int c1 = m1 ? (__ffs(m1)-1)*2 + 1 : 0x7fff;
            int tloc = min(c0, c1);
            tstar = c*64 + tloc;
        }
    }
    if (lane == 0){
        int ts = min(tstar, SEQ_L-1);
        g_tstar[b*D_INNER + d] = ts;
        atomicMin(&g_cutraw[b], ts);
    }
}

// -------- K4: row-gated TF32 GEMM v3 — cp.async double-buffered, k-chunk 16 --------
// Consumes pre-rounded g_xr / g_wr; no cvt, no predicates in the pipeline.
__global__ void k_gemm1(const float* __restrict__ bias){
    int row0 = blockIdx.y*128;
    int b  = row0 / SEQ_L;
    int t0 = row0 % SEQ_L;
    int gate = max(0, g_cutraw[b] - 35);
    if (t0 + 127 < gate) return;
    int n0 = blockIdx.x*128;

    __shared__ float As[2][128][20];   // frag bank (20g+t)%32 — conflict-free
    __shared__ float Ws[2][16][136];   // frag bank (8t+g)%32  — conflict-free

    int tid = threadIdx.x;
    int lane = tid & 31;
    int warp = tid >> 5;
    int wr = warp & 3;
    int wc = warp >> 2;
    int g = lane >> 2, t = lane & 3;

    float acc[2][8][4];
    #pragma unroll
    for (int mf=0;mf<2;mf++)
        #pragma unroll
        for (int nf=0;nf<8;nf++)
            #pragma unroll
            for (int q=0;q<4;q++) acc[mf][nf][q] = 0.f;

    int aRow = tid >> 1;                 // 0..127
    int aK   = (tid & 1) * 8;            // 0 or 8
    int wK   = tid >> 4;                 // 0..15
    int wN   = (tid & 15) * 8;           // 0..120

    uint32_t asA = (uint32_t)__cvta_generic_to_shared(&As[0][0][0]);
    uint32_t asW = (uint32_t)__cvta_generic_to_shared(&Ws[0][0][0]);
    uint32_t dA = asA + (uint32_t)((aRow*20 + aK)*4);
    uint32_t dW = asW + (uint32_t)((wK*136 + wN)*4);
    const float* srcA = g_xr + (size_t)(row0 + aRow)*1024 + aK;
    const float* srcW = g_wr + (size_t)wK*WR_LD + n0 + wN;

    // prologue: chunk 0 into buf 0
    cp16(dA,                srcA);
    cp16(dA + 16,           srcA + 4);
    cp16(dW,                srcW);
    cp16(dW + 16,           srcW + 4);
    cp_commit();

    for (int c = 0; c < 64; c++){
        if (c + 1 < 64){
            int nb = (c+1) & 1;
            const float* sA = srcA + (c+1)*16;
            const float* sW = srcW + (size_t)(c+1)*16*WR_LD;
            cp16(dA + nb*10240,      sA);
            cp16(dA + nb*10240 + 16, sA + 4);
            cp16(dW + nb*8704,       sW);
            cp16(dW + nb*8704 + 16,  sW + 4);
            cp_commit();
            asm volatile("cp.async.wait_group 1;");
        } else {
            asm volatile("cp.async.wait_group 0;");
        }
        __syncthreads();
        int buf = c & 1;
        #pragma unroll
        for (int kb = 0; kb < 16; kb += 8){
            uint32_t afr[2][4];
            #pragma unroll
            for (int mf = 0; mf < 2; mf++){
                int r = wr*32 + mf*16 + g;
                afr[mf][0] = __float_as_uint(As[buf][r  ][kb+t]);
                afr[mf][1] = __float_as_uint(As[buf][r+8][kb+t]);
                afr[mf][2] = __float_as_uint(As[buf][r  ][kb+t+4]);
                afr[mf][3] = __float_as_uint(As[buf][r+8][kb+t+4]);
            }
            uint32_t bfr[8][2];
            #pragma unroll
            for (int nf = 0; nf < 8; nf++){
                int cc = wc*64 + nf*8 + g;
                bfr[nf][0] = __float_as_uint(Ws[buf][kb+t  ][cc]);
                bfr[nf][1] = __float_as_uint(Ws[buf][kb+t+4][cc]);
            }
            #pragma unroll
            for (int mf=0;mf<2;mf++)
                #pragma unroll
                for (int nf=0;nf<8;nf++)
                    mma_tf32(acc[mf][nf], afr[mf], bfr[nf]);
        }
        __syncthreads();
    }
    #pragma unroll
    for (int mf=0;mf<2;mf++){
        int rA = row0 + wr*32 + mf*16 + g;
        #pragma unroll
        for (int nf=0;nf<8;nf++){
            int c = n0 + wc*64 + nf*8 + 2*t;
            if (c < NC1){
                float b0 = bias[COL_OFF+c], b1 = bias[COL_OFF+c+1];
                *(float2*)(g_projT + (size_t)rA*NC1 + c) =
                    make_float2(acc[mf][nf][0] + b0, acc[mf][nf][1] + b1);
                *(float2*)(g_projT + (size_t)(rA+8)*NC1 + c) =
                    make_float2(acc[mf][nf][2] + b0, acc[mf][nf][3] + b1);
            }
        }
    }
}

// -------- K5: causal depthwise conv4 + SiLU — compacted grid --------
__global__ void k_conv(const float* __restrict__ cw, const float* __restrict__ cb){
    int d0 = blockIdx.y*32, b = blockIdx.z;
    int lo = g_cutraw[b] & ~31;
    int t0 = SEQ_L - 320 + blockIdx.x*32;
    __shared__ float xs[35][33];
    __shared__ float ws[32][4];
    __shared__ float cbs[32];
    int tid = threadIdx.x;
    for (int i = tid; i < 32*4; i += 256){
        int dd = i >> 2, k = i & 3;
        ws[dd][k] = cw[(d0+dd)*4 + k];
    }
    if (tid < 32) cbs[tid] = cb[d0 + tid];

    int nExtra = 0;
    if (blockIdx.x == 0 && lo < SEQ_L - 320)
        nExtra = (SEQ_L - 320 - lo + 31) >> 5;
    int total = 1 + nExtra;
    for (int it = 0; it < total; it++){
        int tb = (it == 0) ? t0 : lo + (it-1)*32;
        if (it == 0 && t0 + 31 < lo) continue;
        __syncthreads();
        for (int i = tid; i < 35*32; i += 256){
            int tt = i >> 5, dd = i & 31;
            int t = tb - 3 + tt;
            xs[tt][dd] = (t >= 0) ? g_projT[(size_t)(b*SEQ_L + t)*NC1 + d0 + dd] : 0.f;
        }
        __syncthreads();
        for (int o = tid; o < 32*32; o += 256){
            int dd = o >> 5, tl = o & 31;
            float acc = cbs[dd];
            #pragma unroll
            for (int k = 0; k < 4; k++) acc = fmaf(ws[dd][k], xs[tl+k][dd], acc);
            float sg = 1.f / (1.f + __expf(-acc));
            g_xc[((size_t)(b*D_INNER + d0 + dd))*SEQ_L + tb + tl] = acc * sg;
        }
    }
}

// -------- K6: final-state reduction + gates — one warp per (b,d) row --------
__global__ void k_state(const float* __restrict__ A_log, const float* __restrict__ Dp){
    int tid = threadIdx.x;
    int lane = tid & 31;
    int d = blockIdx.x*8 + (tid >> 5);
    int b = blockIdx.y;
    size_t base = ((size_t)(b*D_INNER + d))*SEQ_L;

    float av = (lane < 16) ? -__expf(A_log[d*16 + lane]) : 0.f;
    float cv = (lane < 16) ? g_Cl[b*16 + lane] : 0.f;
    float A_[16], C_[16];
    #pragma unroll
    for (int n = 0; n < 16; n++){
        A_[n] = __shfl_sync(0xffffffffu, av, n);
        C_[n] = __shfl_sync(0xffffffffu, cv, n);
    }

    int ts = g_tstar[b*D_INNER + d];
    float acc[16];
    #pragma unroll
    for (int n = 0; n < 16; n++) acc[n] = 0.f;

    int nIter = (SEQ_L - ts + 31) >> 5;
    for (int it = 0; it < nIter; it++){
        int t = ts + it*32 + lane;
        bool valid = t < SEQ_L;
        float R = 0.f, u = 0.f, Rv = 3.4e38f;
        float Bv[16];
        #pragma unroll
        for (int n = 0; n < 16; n++) Bv[n] = 0.f;
        if (valid){
            R = g_R[base + t];
            u = g_dt[base + t] * g_xc[base + t];
            Rv = R;
            const float4* bp = (const float4*)(g_projT + (size_t)(b*SEQ_L + t)*NC1 + 2048);
            float4 b0 = bp[0], b1 = bp[1], b2 = bp[2], b3 = bp[3];
            Bv[0]=b0.x; Bv[1]=b0.y; Bv[2]=b0.z; Bv[3]=b0.w;
            Bv[4]=b1.x; Bv[5]=b1.y; Bv[6]=b1.z; Bv[7]=b1.w;
            Bv[8]=b2.x; Bv[9]=b2.y; Bv[10]=b2.z; Bv[11]=b2.w;
            Bv[12]=b3.x; Bv[13]=b3.y; Bv[14]=b3.z; Bv[15]=b3.w;
        }
        float Rmin = Rv;
        #pragma unroll
        for (int off = 16; off > 0; off >>= 1)
            Rmin = fminf(Rmin, __shfl_xor_sync(0xffffffffu, Rmin, off));
        #pragma unroll
        for (int n = 0; n < 16; n++){
            if (A_[n]*Rmin > -30.f){
                acc[n] = fmaf(__expf(A_[n]*R)*u, Bv[n], acc[n]);
            }
        }
    }
    #pragma unroll
    for (int n = 0; n < 16; n++){
        #pragma unroll
        for (int off = 16; off > 0; off >>= 1)
            acc[n] += __shfl_xor_sync(0xffffffffu, acc[n], off);
    }
    if (lane == 0){
        float y = 0.f;
        #pragma unroll
        for (int n = 0; n < 16; n++) y = fmaf(acc[n], C_[n], y);
        y += g_xc[base + SEQ_L - 1] * Dp[d];
        float z = g_z[b*D_INNER + d];
        float sg = 1.f / (1.f + __expf(-z));
        y *= z * sg;
        g_fm[b*D_INNER + d] = y;
    }
}

// -------- K7: fused layernorm + out_proj — 64 blocks (16 cols, 16 k-chunks) --------
__global__ void k_out(const float* __restrict__ W, const float* __restrict__ ob,
                      const float* __restrict__ g, const float* __restrict__ beta,
                      float* __restrict__ out){
    int tid = threadIdx.x;
    int jc = blockIdx.x;
    __shared__ float xn[B_SZ][D_INNER];
    __shared__ float r1[256], r2[256];
    __shared__ float pr[16][16][4];
    __shared__ float mu_s[4], rs_s[4];

    for (int b = 0; b < B_SZ; b++){
        float s1 = 0.f, s2 = 0.f;
        for (int i = tid; i < D_INNER; i += 256){
            float v = g_fm[b*D_INNER + i];
            xn[b][i] = v;
            s1 += v; s2 += v*v;
        }
        r1[tid] = s1; r2[tid] = s2;
        __syncthreads();
        for (int off = 128; off > 0; off >>= 1){
            if (tid < off){ r1[tid] += r1[tid+off]; r2[tid] += r2[tid+off]; }
            __syncthreads();
        }
        if (tid == 0){
            float mu = r1[0] / D_INNER;
            float var = r2[0] / D_INNER - mu*mu;
            mu_s[b] = mu;
            rs_s[b] = rsqrtf(var + 1e-5f);
        }
        __syncthreads();
    }
    for (int i = tid; i < D_INNER; i += 256){
        float gg = g[i], bb = beta[i];
        #pragma unroll
        for (int b = 0; b < B_SZ; b++)
            xn[b][i] = (xn[b][i] - mu_s[b]) * rs_s[b] * gg + bb;
    }
    __syncthreads();

    int jl = tid & 15, kq = tid >> 4;
    int j = jc*16 + jl;
    float a0=0.f,a1=0.f,a2=0.f,a3=0.f;
    const float* wp = W + (size_t)(kq*128)*D_MODEL + j;
    #pragma unroll 8
    for (int k = 0; k < 128; k++){
        float w = wp[(size_t)k*D_MODEL];
        int dd = kq*128 + k;
        a0 = fmaf(xn[0][dd], w, a0);
        a1 = fmaf(xn[1][dd], w, a1);
        a2 = fmaf(xn[2][dd], w, a2);
        a3 = fmaf(xn[3][dd], w, a3);
    }
    pr[kq][jl][0]=a0; pr[kq][jl][1]=a1; pr[kq][jl][2]=a2; pr[kq][jl][3]=a3;
    __syncthreads();
    if (tid < 64){
        int jl2 = tid & 15, b = tid >> 4;
        float s = ob[jc*16 + jl2];
        #pragma unroll
        for (int q = 0; q < 16; q++) s += pr[q][jl2][b];
        out[b*D_MODEL + jc*16 + jl2] = s;
    }
}

extern "C" void kernel_launch(void* const* d_in, const int* in_sizes, int n_in,
                              void* d_out, int out_size){
    const float* x    = (const float*)d_in[0];
    const float* W1   = (const float*)d_in[1];
    const float* b1   = (const float*)d_in[2];
    const float* cw   = (const float*)d_in[3];
    const float* cb   = (const float*)d_in[4];
    const float* W2   = (const float*)d_in[5];
    const float* b2   = (const float*)d_in[6];
    const float* Alog = (const float*)d_in[7];
    const float* Dp   = (const float*)d_in[8];
    const float* Wo   = (const float*)d_in[9];
    const float* ob   = (const float*)d_in[10];
    const float* lg   = (const float*)d_in[11];
    const float* lb   = (const float*)d_in[12];
    float* out = (float*)d_out;

    // gemm1 kept at launch index 3 (ncu capture slot); pre-round fused into k_dtr
    k_dtr  <<<1792,              256>>>(x, W1);
    k_dt   <<<dim3(32,32,4),     256>>>(W2, b2);
    k_scan <<<dim3(256,4),       256>>>(Alog);
    k_gemm1<<<dim3(17,64),       256>>>(b1);
    k_zc   <<<dim3(33,4),        256>>>(x, W1, b1);
    k_conv <<<dim3(10,64,4),     256>>>(cw, cb);
    k_state<<<dim3(256,4),       256>>>(Alog, Dp);
    k_out  <<<64,                256>>>(Wo, ob, lg, lb, out);
}

// round 13
// speedup vs baseline: 1.4061x; 1.4061x over previous
#include <cuda_runtime.h>
#include <math.h>
#include <stdint.h>

#define B_SZ    4
#define SEQ_L   2048
#define D_MODEL 1024
#define D_INNER 2048
#define D_STATE 16
#define DT_RANK 64
#define IN_DIM  4192
#define NROWS   (B_SZ*SEQ_L)     /* 8192 */
#define NC1     2064             /* x_in(2048) + B(16) columns */
#define COL_OFF 2048
#define WR_LD   2176             /* g_wr row stride (floats), cols >=2064 zero */
#define MY_INT_MAX 0x7fffffff

// ---------------- scratch (static device, no allocs) ----------------
__device__ float g_projT[(size_t)NROWS*NC1];            // x_in | B  (row-major, ld=NC1)
__device__ float g_xr[(size_t)NROWS*D_MODEL];           // tf32-rounded x
__device__ float g_wr[(size_t)D_MODEL*WR_LD];           // tf32-rounded W[:,2048:4112], zero-padded
__device__ float g_dtr[NROWS*DT_RANK];                  // tf32-rounded dtr (only k_dt consumes)
__device__ float g_dt[(size_t)B_SZ*D_INNER*SEQ_L];      // (b,d,t)
__device__ float g_R [(size_t)B_SZ*D_INNER*SEQ_L];      // suffix sums, tail only
__device__ float g_xc[(size_t)B_SZ*D_INNER*SEQ_L];      // silu(conv), tail only
__device__ float g_csum[B_SZ*32*D_INNER];               // per-64-chunk dt sums
__device__ float g_z [B_SZ*D_INNER];
__device__ float g_Cl[B_SZ*D_STATE];
__device__ int   g_tstar[B_SZ*D_INNER];
__device__ int   g_cutraw[B_SZ];
__device__ float g_fm[B_SZ*D_INNER];

__device__ __forceinline__ float softplusf(float x){
    return (x > 15.f) ? x : log1pf(__expf(x));
}

__device__ __forceinline__ float tf32r(float x){
    uint32_t r;
    asm("cvt.rna.tf32.f32 %0, %1;" : "=r"(r) : "f"(x));
    return __uint_as_float(r);
}

__device__ __forceinline__ void mma_tf32(float* c, const uint32_t* a, const uint32_t* b){
    asm volatile(
        "mma.sync.aligned.m16n8k8.row.col.f32.tf32.tf32.f32 "
        "{%0,%1,%2,%3}, {%4,%5,%6,%7}, {%8,%9}, {%0,%1,%2,%3};"
        : "+f"(c[0]), "+f"(c[1]), "+f"(c[2]), "+f"(c[3])
        : "r"(a[0]), "r"(a[1]), "r"(a[2]), "r"(a[3]), "r"(b[0]), "r"(b[1]));
}

__device__ __forceinline__ void cp16(uint32_t dst, const void* src){
    asm volatile("cp.async.cg.shared.global [%0], [%1], 16;" :: "r"(dst), "l"(src));
}
__device__ __forceinline__ void cp_commit(){
    asm volatile("cp.async.commit_group;");
}

// -------- K0: z and C for the LAST timestep only (split-K) --------
__global__ void k_zc(const float* __restrict__ x, const float* __restrict__ W,
                     const float* __restrict__ bias){
    int b = blockIdx.y;
    int tid = threadIdx.x;
    int cl = tid & 63, kq = tid >> 6;
    int c = blockIdx.x*64 + cl;
    __shared__ float xs[1024];
    __shared__ float p[4][64];
    const float* xrow = x + ((size_t)(b*SEQ_L + SEQ_L-1))*D_MODEL;
    for (int i = tid; i < 1024; i += 256) xs[i] = xrow[i];
    __syncthreads();
    float acc = 0.f;
    if (c < 2064){
        int wcol = (c < 2048) ? c : (4112 + (c - 2048));
        const float* wp = W + (size_t)(kq*256)*IN_DIM + wcol;
        #pragma unroll 8
        for (int k = 0; k < 256; k++) acc += xs[kq*256 + k] * wp[(size_t)k*IN_DIM];
    }
    p[kq][cl] = acc;
    __syncthreads();
    if (tid < 64){
        int cc = blockIdx.x*64 + tid;
        if (cc < 2064){
            float s = p[0][tid] + p[1][tid] + p[2][tid] + p[3][tid];
            int wcol = (cc < 2048) ? cc : (4112 + (cc - 2048));
            s += bias[wcol];
            if (cc < 2048) g_z[b*D_INNER + cc] = s;
            else           g_Cl[b*D_STATE + (cc-2048)] = s;
        }
    }
}

// -------- K1: dtr GEMM (blocks 0..255, tf32-rounded output) + pre-round x / W slab --------
__global__ void k_dtr(const float* __restrict__ x, const float* __restrict__ W){
    int tid = threadIdx.x;
    if (blockIdx.x >= 256){
        int pid = blockIdx.x - 256;
        if (pid < 1024){
            for (size_t i = (size_t)pid*256 + tid; i < 2097152u; i += 262144u){
                float4 v = ((const float4*)x)[i];
                float4 o = make_float4(tf32r(v.x), tf32r(v.y), tf32r(v.z), tf32r(v.w));
                ((float4*)g_xr)[i] = o;
            }
        } else {
            int p2 = pid - 1024;   // 0..511
            for (size_t i = (size_t)p2*256 + tid; i < 557056u; i += 131072u){
                int k  = (int)(i / 544);
                int c4 = (int)(i % 544);
                float4 o = make_float4(0.f,0.f,0.f,0.f);
                if (c4 < 516){
                    float4 v = *(const float4*)(W + (size_t)k*IN_DIM + COL_OFF + c4*4);
                    o = make_float4(tf32r(v.x), tf32r(v.y), tf32r(v.z), tf32r(v.w));
                }
                ((float4*)g_wr)[(size_t)k*544 + c4] = o;
            }
        }
        return;
    }
    int r0 = blockIdx.x * 32;
    if (blockIdx.x == 0 && tid < B_SZ) g_cutraw[tid] = MY_INT_MAX;
    __shared__ float xs[32][64];
    __shared__ float ws[64][64];
    int rowq = tid >> 4;
    int cg   = tid & 15;
    float acc0[4] = {0,0,0,0};
    float acc1[4] = {0,0,0,0};
    for (int k0 = 0; k0 < 1024; k0 += 64){
        __syncthreads();
        float4 a0 = *(const float4*)(x + (size_t)(r0+rowq)*1024 + k0 + cg*4);
        float4 a1 = *(const float4*)(x + (size_t)(r0+rowq+16)*1024 + k0 + cg*4);
        *(float4*)&xs[rowq][cg*4]    = a0;
        *(float4*)&xs[rowq+16][cg*4] = a1;
        #pragma unroll
        for (int jj = 0; jj < 4; jj++){
            int k = (tid>>4) + jj*16;
            *(float4*)&ws[k][cg*4] =
                *(const float4*)(W + (size_t)(k0+k)*IN_DIM + 4128 + cg*4);
        }
        __syncthreads();
        #pragma unroll
        for (int k = 0; k < 64; k++){
            float xa = xs[rowq][k], xb = xs[rowq+16][k];
            float4 w = *(float4*)&ws[k][cg*4];
            acc0[0] = fmaf(xa, w.x, acc0[0]); acc0[1] = fmaf(xa, w.y, acc0[1]);
            acc0[2] = fmaf(xa, w.z, acc0[2]); acc0[3] = fmaf(xa, w.w, acc0[3]);
            acc1[0] = fmaf(xb, w.x, acc1[0]); acc1[1] = fmaf(xb, w.y, acc1[1]);
            acc1[2] = fmaf(xb, w.z, acc1[2]); acc1[3] = fmaf(xb, w.w, acc1[3]);
        }
    }
    *(float4*)(g_dtr + (size_t)(r0+rowq)*64 + cg*4) =
        make_float4(tf32r(acc0[0]),tf32r(acc0[1]),tf32r(acc0[2]),tf32r(acc0[3]));
    *(float4*)(g_dtr + (size_t)(r0+rowq+16)*64 + cg*4) =
        make_float4(tf32r(acc1[0]),tf32r(acc1[1]),tf32r(acc1[2]),tf32r(acc1[3]));
}

// -------- K2: dt via TF32 MMA — 128 t-rows x 64 d-cols per CTA, K=64 --------
// Outputs softplus(logits) transposed (b,d,t) + deterministic 64-chunk sums.
__global__ void k_dt(const float* __restrict__ W2, const float* __restrict__ b2){
    int d0 = blockIdx.x*64;
    int row0 = blockIdx.y*128;
    int b = row0 >> 11;
    int t0 = row0 & (SEQ_L-1);

    __shared__ float As[128][36];   // dtr tile (pre-rounded) — frag bank (4g+t) conflict-free
    __shared__ float Ws[32][72];    // W2 k-chunk — frag bank (8t+g) conflict-free
    __shared__ float bs[64];
    __shared__ float sm[4][64];     // per-warp-row column sums

    int tid = threadIdx.x;
    int lane = tid & 31;
    int warp = tid >> 5;
    int wr = warp & 3;              // 4 warp-rows * 32 t
    int wc = warp >> 2;             // 2 warp-cols * 32 d
    int g = lane >> 2, t = lane & 3;

    if (tid < 64) bs[tid] = b2[d0 + tid];

    float acc[2][4][4];
    #pragma unroll
    for (int mf=0;mf<2;mf++)
        #pragma unroll
        for (int nf=0;nf<4;nf++)
            #pragma unroll
            for (int q=0;q<4;q++) acc[mf][nf][q] = 0.f;

    int aRow = tid >> 1;
    int aK   = (tid & 1) * 16;
    int wK   = tid >> 3;            // 0..31
    int wN   = (tid & 7) * 8;       // 0..56

    #pragma unroll
    for (int kc = 0; kc < 64; kc += 32){
        __syncthreads();
        #pragma unroll
        for (int jj = 0; jj < 4; jj++)
            *(float4*)&As[aRow][aK+jj*4] =
                *(const float4*)(g_dtr + (size_t)(row0+aRow)*64 + kc + aK + jj*4);
        #pragma unroll
        for (int jj = 0; jj < 2; jj++){
            float4 v = *(const float4*)(W2 + (size_t)(kc+wK)*D_INNER + d0 + wN + jj*4);
            Ws[wK][wN+jj*4+0] = tf32r(v.x);
            Ws[wK][wN+jj*4+1] = tf32r(v.y);
            Ws[wK][wN+jj*4+2] = tf32r(v.z);
            Ws[wK][wN+jj*4+3] = tf32r(v.w);
        }
        __syncthreads();
        #pragma unroll
        for (int kb = 0; kb < 32; kb += 8){
            uint32_t afr[2][4];
            #pragma unroll
            for (int mf = 0; mf < 2; mf++){
                int r = wr*32 + mf*16 + g;
                afr[mf][0] = __float_as_uint(As[r  ][kb+t]);
                afr[mf][1] = __float_as_uint(As[r+8][kb+t]);
                afr[mf][2] = __float_as_uint(As[r  ][kb+t+4]);
                afr[mf][3] = __float_as_uint(As[r+8][kb+t+4]);
            }
            uint32_t bfr[4][2];
            #pragma unroll
            for (int nf = 0; nf < 4; nf++){
                int c = wc*32 + nf*8 + g;
                bfr[nf][0] = __float_as_uint(Ws[kb+t  ][c]);
                bfr[nf][1] = __float_as_uint(Ws[kb+t+4][c]);
            }
            #pragma unroll
            for (int mf=0;mf<2;mf++)
                #pragma unroll
                for (int nf=0;nf<4;nf++)
                    mma_tf32(acc[mf][nf], afr[mf], bfr[nf]);
        }
    }

    // epilogue: softplus(+bias), store transposed, per-column partial sums
    float sp[2][4][4];
    #pragma unroll
    for (int mf=0;mf<2;mf++){
        int tl = wr*32 + mf*16 + g;          // t within block (rows tl, tl+8)
        #pragma unroll
        for (int nf=0;nf<4;nf++){
            int c = wc*32 + nf*8 + 2*t;
            float b0 = bs[c], b1 = bs[c+1];
            sp[mf][nf][0] = softplusf(acc[mf][nf][0] + b0);
            sp[mf][nf][1] = softplusf(acc[mf][nf][1] + b1);
            sp[mf][nf][2] = softplusf(acc[mf][nf][2] + b0);
            sp[mf][nf][3] = softplusf(acc[mf][nf][3] + b1);
            int d = d0 + c;
            g_dt[((size_t)(b*D_INNER + d  ))*SEQ_L + t0 + tl]     = sp[mf][nf][0];
            g_dt[((size_t)(b*D_INNER + d+1))*SEQ_L + t0 + tl]     = sp[mf][nf][1];
            g_dt[((size_t)(b*D_INNER + d  ))*SEQ_L + t0 + tl + 8] = sp[mf][nf][2];
            g_dt[((size_t)(b*D_INNER + d+1))*SEQ_L + t0 + tl + 8] = sp[mf][nf][3];
        }
    }
    // per-lane: sum of this lane's 4 t-values per column, then xor-butterfly over g
    #pragma unroll
    for (int nf = 0; nf < 4; nf++){
        float c0 = sp[0][nf][0] + sp[0][nf][2] + sp[1][nf][0] + sp[1][nf][2];
        float c1 = sp[0][nf][1] + sp[0][nf][3] + sp[1][nf][1] + sp[1][nf][3];
        #pragma unroll
        for (int off = 4; off < 32; off <<= 1){
            c0 += __shfl_xor_sync(0xffffffffu, c0, off);
            c1 += __shfl_xor_sync(0xffffffffu, c1, off);
        }
        if (g == 0){                          // lane == t
            int c = wc*32 + nf*8 + 2*t;
            sm[wr][c]   = c0;                 // sum over this warp-row's 32 t
            sm[wr][c+1] = c1;
        }
    }
    __syncthreads();
    if (tid < 128){
        int half = tid >> 6;                  // 0: rows 0..63, 1: rows 64..127
        int col  = tid & 63;
        int chunk = (t0 >> 6) + half;
        g_csum[(b*32 + chunk)*D_INNER + d0 + col] =
            sm[half*2][col] + sm[half*2+1][col];
    }
}

// -------- K3: scan v2 — csum-driven; one warp per (b,d) row --------
__global__ void k_scan(const float* __restrict__ A_log){
    int tid = threadIdx.x;
    int lane = tid & 31;
    int d = blockIdx.x*8 + (tid >> 5);
    int b = blockIdx.y;
    size_t base = ((size_t)(b*D_INNER + d))*SEQ_L;

    float a = (lane < 16) ? -__expf(A_log[d*16 + lane]) : -3.4e38f;
    #pragma unroll
    for (int off = 16; off > 0; off >>= 1)
        a = fmaxf(a, __shfl_xor_sync(0xffffffffu, a, off));
    float Th = -32.f / a;

    float cs = g_csum[(b*32 + lane)*D_INNER + d];
    float S = cs;
    #pragma unroll
    for (int off = 1; off < 32; off <<= 1){
        float v = __shfl_down_sync(0xffffffffu, S, off);
        if (lane + off < 32) S += v;
    }
    float Snext = __shfl_down_sync(0xffffffffu, S, 1);
    if (lane == 31) Snext = 0.f;
    unsigned liveMask = __ballot_sync(0xffffffffu, Snext < Th);
    int cstar = __ffs(liveMask) - 1;

    int tstar = SEQ_L - 1;
    for (int c = cstar; c < 32; c++){
        float Sn = __shfl_sync(0xffffffffu, Snext, c);
        float2 dv = *(const float2*)(g_dt + base + c*64 + lane*2);
        float pair = dv.x + dv.y;
        float P = pair;
        #pragma unroll
        for (int off = 1; off < 32; off <<= 1){
            float v = __shfl_down_sync(0xffffffffu, P, off);
            if (lane + off < 32) P += v;
        }
        float tailp = P - pair;
        float R1 = Sn + tailp;
        float R0 = R1 + dv.y;
        *(float2*)(g_R + base + c*64 + lane*2) = make_float2(R0, R1);
        if (c == cstar){
            unsigned m0 = __ballot_sync(0xffffffffu, R0 < Th);
            unsigned m1 = __ballot_sync(0xffffffffu, R1 < Th);
            int c0 = m0 ? (__ffs(m0)-1)*2     : 0x7fff;
            int c1 = m1 ? (__ffs(m1)-1)*2 + 1 : 0x7fff;
            int tloc = min(c0, c1);
            tstar = c*64 + tloc;
        }
    }
    if (lane == 0){
        int ts = min(tstar, SEQ_L-1);
        g_tstar[b*D_INNER + d] = ts;
        atomicMin(&g_cutraw[b], ts);
    }
}

// -------- K4: row-gated TF32 GEMM v3 — cp.async double-buffered, k-chunk 16 --------
__global__ void k_gemm1(const float* __restrict__ bias){
    int row0 = blockIdx.y*128;
    int b  = row0 / SEQ_L;
    int t0 = row0 % SEQ_L;
    int gate = max(0, g_cutraw[b] - 35);
    if (t0 + 127 < gate) return;
    int n0 = blockIdx.x*128;

    __shared__ float As[2][128][20];
    __shared__ float Ws[2][16][136];

    int tid = threadIdx.x;
    int lane = tid & 31;
    int warp = tid >> 5;
    int wr = warp & 3;
    int wc = warp >> 2;
    int g = lane >> 2, t = lane & 3;

    float acc[2][8][4];
    #pragma unroll
    for (int mf=0;mf<2;mf++)
        #pragma unroll
        for (int nf=0;nf<8;nf++)
            #pragma unroll
            for (int q=0;q<4;q++) acc[mf][nf][q] = 0.f;

    int aRow = tid >> 1;
    int aK   = (tid & 1) * 8;
    int wK   = tid >> 4;
    int wN   = (tid & 15) * 8;

    uint32_t asA = (uint32_t)__cvta_generic_to_shared(&As[0][0][0]);
    uint32_t asW = (uint32_t)__cvta_generic_to_shared(&Ws[0][0][0]);
    uint32_t dA = asA + (uint32_t)((aRow*20 + aK)*4);
    uint32_t dW = asW + (uint32_t)((wK*136 + wN)*4);
    const float* srcA = g_xr + (size_t)(row0 + aRow)*1024 + aK;
    const float* srcW = g_wr + (size_t)wK*WR_LD + n0 + wN;

    cp16(dA,                srcA);
    cp16(dA + 16,           srcA + 4);
    cp16(dW,                srcW);
    cp16(dW + 16,           srcW + 4);
    cp_commit();

    for (int c = 0; c < 64; c++){
        if (c + 1 < 64){
            int nb = (c+1) & 1;
            const float* sA = srcA + (c+1)*16;
            const float* sW = srcW + (size_t)(c+1)*16*WR_LD;
            cp16(dA + nb*10240,      sA);
            cp16(dA + nb*10240 + 16, sA + 4);
            cp16(dW + nb*8704,       sW);
            cp16(dW + nb*8704 + 16,  sW + 4);
            cp_commit();
            asm volatile("cp.async.wait_group 1;");
        } else {
            asm volatile("cp.async.wait_group 0;");
        }
        __syncthreads();
        int buf = c & 1;
        #pragma unroll
        for (int kb = 0; kb < 16; kb += 8){
            uint32_t afr[2][4];
            #pragma unroll
            for (int mf = 0; mf < 2; mf++){
                int r = wr*32 + mf*16 + g;
                afr[mf][0] = __float_as_uint(As[buf][r  ][kb+t]);
                afr[mf][1] = __float_as_uint(As[buf][r+8][kb+t]);
                afr[mf][2] = __float_as_uint(As[buf][r  ][kb+t+4]);
                afr[mf][3] = __float_as_uint(As[buf][r+8][kb+t+4]);
            }
            uint32_t bfr[8][2];
            #pragma unroll
            for (int nf = 0; nf < 8; nf++){
                int cc = wc*64 + nf*8 + g;
                bfr[nf][0] = __float_as_uint(Ws[buf][kb+t  ][cc]);
                bfr[nf][1] = __float_as_uint(Ws[buf][kb+t+4][cc]);
            }
            #pragma unroll
            for (int mf=0;mf<2;mf++)
                #pragma unroll
                for (int nf=0;nf<8;nf++)
                    mma_tf32(acc[mf][nf], afr[mf], bfr[nf]);
        }
        __syncthreads();
    }
    #pragma unroll
    for (int mf=0;mf<2;mf++){
        int rA = row0 + wr*32 + mf*16 + g;
        #pragma unroll
        for (int nf=0;nf<8;nf++){
            int c = n0 + wc*64 + nf*8 + 2*t;
            if (c < NC1){
                float b0 = bias[COL_OFF+c], b1 = bias[COL_OFF+c+1];
                *(float2*)(g_projT + (size_t)rA*NC1 + c) =
                    make_float2(acc[mf][nf][0] + b0, acc[mf][nf][1] + b1);
                *(float2*)(g_projT + (size_t)(rA+8)*NC1 + c) =
                    make_float2(acc[mf][nf][2] + b0, acc[mf][nf][3] + b1);
            }
        }
    }
}

// -------- K5: causal depthwise conv4 + SiLU — compacted grid --------
__global__ void k_conv(const float* __restrict__ cw, const float* __restrict__ cb){
    int d0 = blockIdx.y*32, b = blockIdx.z;
    int lo = g_cutraw[b] & ~31;
    int t0 = SEQ_L - 320 + blockIdx.x*32;
    __shared__ float xs[35][33];
    __shared__ float ws[32][4];
    __shared__ float cbs[32];
    int tid = threadIdx.x;
    for (int i = tid; i < 32*4; i += 256){
        int dd = i >> 2, k = i & 3;
        ws[dd][k] = cw[(d0+dd)*4 + k];
    }
    if (tid < 32) cbs[tid] = cb[d0 + tid];

    int nExtra = 0;
    if (blockIdx.x == 0 && lo < SEQ_L - 320)
        nExtra = (SEQ_L - 320 - lo + 31) >> 5;
    int total = 1 + nExtra;
    for (int it = 0; it < total; it++){
        int tb = (it == 0) ? t0 : lo + (it-1)*32;
        if (it == 0 && t0 + 31 < lo) continue;
        __syncthreads();
        for (int i = tid; i < 35*32; i += 256){
            int tt = i >> 5, dd = i & 31;
            int t = tb - 3 + tt;
            xs[tt][dd] = (t >= 0) ? g_projT[(size_t)(b*SEQ_L + t)*NC1 + d0 + dd] : 0.f;
        }
        __syncthreads();
        for (int o = tid; o < 32*32; o += 256){
            int dd = o >> 5, tl = o & 31;
            float acc = cbs[dd];
            #pragma unroll
            for (int k = 0; k < 4; k++) acc = fmaf(ws[dd][k], xs[tl+k][dd], acc);
            float sg = 1.f / (1.f + __expf(-acc));
            g_xc[((size_t)(b*D_INNER + d0 + dd))*SEQ_L + tb + tl] = acc * sg;
        }
    }
}

// -------- K6: final-state reduction + gates — one warp per (b,d) row --------
__global__ void k_state(const float* __restrict__ A_log, const float* __restrict__ Dp){
    int tid = threadIdx.x;
    int lane = tid & 31;
    int d = blockIdx.x*8 + (tid >> 5);
    int b = blockIdx.y;
    size_t base = ((size_t)(b*D_INNER + d))*SEQ_L;

    float av = (lane < 16) ? -__expf(A_log[d*16 + lane]) : 0.f;
    float cv = (lane < 16) ? g_Cl[b*16 + lane] : 0.f;
    float A_[16], C_[16];
    #pragma unroll
    for (int n = 0; n < 16; n++){
        A_[n] = __shfl_sync(0xffffffffu, av, n);
        C_[n] = __shfl_sync(0xffffffffu, cv, n);
    }

    int ts = g_tstar[b*D_INNER + d];
    float acc[16];
    #pragma unroll
    for (int n = 0; n < 16; n++) acc[n] = 0.f;

    int nIter = (SEQ_L - ts + 31) >> 5;
    for (int it = 0; it < nIter; it++){
        int t = ts + it*32 + lane;
        bool valid = t < SEQ_L;
        float R = 0.f, u = 0.f, Rv = 3.4e38f;
        float Bv[16];
        #pragma unroll
        for (int n = 0; n < 16; n++) Bv[n] = 0.f;
        if (valid){
            R = g_R[base + t];
            u = g_dt[base + t] * g_xc[base + t];
            Rv = R;
            const float4* bp = (const float4*)(g_projT + (size_t)(b*SEQ_L + t)*NC1 + 2048);
            float4 b0 = bp[0], b1 = bp[1], b2 = bp[2], b3 = bp[3];
            Bv[0]=b0.x; Bv[1]=b0.y; Bv[2]=b0.z; Bv[3]=b0.w;
            Bv[4]=b1.x; Bv[5]=b1.y; Bv[6]=b1.z; Bv[7]=b1.w;
            Bv[8]=b2.x; Bv[9]=b2.y; Bv[10]=b2.z; Bv[11]=b2.w;
            Bv[12]=b3.x; Bv[13]=b3.y; Bv[14]=b3.z; Bv[15]=b3.w;
        }
        float Rmin = Rv;
        #pragma unroll
        for (int off = 16; off > 0; off >>= 1)
            Rmin = fminf(Rmin, __shfl_xor_sync(0xffffffffu, Rmin, off));
        #pragma unroll
        for (int n = 0; n < 16; n++){
            if (A_[n]*Rmin > -30.f){
                acc[n] = fmaf(__expf(A_[n]*R)*u, Bv[n], acc[n]);
            }
        }
    }
    #pragma unroll
    for (int n = 0; n < 16; n++){
        #pragma unroll
        for (int off = 16; off > 0; off >>= 1)
            acc[n] += __shfl_xor_sync(0xffffffffu, acc[n], off);
    }
    if (lane == 0){
        float y = 0.f;
        #pragma unroll
        for (int n = 0; n < 16; n++) y = fmaf(acc[n], C_[n], y);
        y += g_xc[base + SEQ_L - 1] * Dp[d];
        float z = g_z[b*D_INNER + d];
        float sg = 1.f / (1.f + __expf(-z));
        y *= z * sg;
        g_fm[b*D_INNER + d] = y;
    }
}

// -------- K7: fused layernorm + out_proj — 64 blocks (16 cols, 16 k-chunks) --------
__global__ void k_out(const float* __restrict__ W, const float* __restrict__ ob,
                      const float* __restrict__ g, const float* __restrict__ beta,
                      float* __restrict__ out){
    int tid = threadIdx.x;
    int jc = blockIdx.x;
    __shared__ float xn[B_SZ][D_INNER];
    __shared__ float r1[256], r2[256];
    __shared__ float pr[16][16][4];
    __shared__ float mu_s[4], rs_s[4];

    for (int b = 0; b < B_SZ; b++){
        float s1 = 0.f, s2 = 0.f;
        for (int i = tid; i < D_INNER; i += 256){
            float v = g_fm[b*D_INNER + i];
            xn[b][i] = v;
            s1 += v; s2 += v*v;
        }
        r1[tid] = s1; r2[tid] = s2;
        __syncthreads();
        for (int off = 128; off > 0; off >>= 1){
            if (tid < off){ r1[tid] += r1[tid+off]; r2[tid] += r2[tid+off]; }
            __syncthreads();
        }
        if (tid == 0){
            float mu = r1[0] / D_INNER;
            float var = r2[0] / D_INNER - mu*mu;
            mu_s[b] = mu;
            rs_s[b] = rsqrtf(var + 1e-5f);
        }
        __syncthreads();
    }
    for (int i = tid; i < D_INNER; i += 256){
        float gg = g[i], bb = beta[i];
        #pragma unroll
        for (int b = 0; b < B_SZ; b++)
            xn[b][i] = (xn[b][i] - mu_s[b]) * rs_s[b] * gg + bb;
    }
    __syncthreads();

    int jl = tid & 15, kq = tid >> 4;
    int j = jc*16 + jl;
    float a0=0.f,a1=0.f,a2=0.f,a3=0.f;
    const float* wp = W + (size_t)(kq*128)*D_MODEL + j;
    #pragma unroll 8
    for (int k = 0; k < 128; k++){
        float w = wp[(size_t)k*D_MODEL];
        int dd = kq*128 + k;
        a0 = fmaf(xn[0][dd], w, a0);
        a1 = fmaf(xn[1][dd], w, a1);
        a2 = fmaf(xn[2][dd], w, a2);
        a3 = fmaf(xn[3][dd], w, a3);
    }
    pr[kq][jl][0]=a0; pr[kq][jl][1]=a1; pr[kq][jl][2]=a2; pr[kq][jl][3]=a3;
    __syncthreads();
    if (tid < 64){
        int jl2 = tid & 15, b = tid >> 4;
        float s = ob[jc*16 + jl2];
        #pragma unroll
        for (int q = 0; q < 16; q++) s += pr[q][jl2][b];
        out[b*D_MODEL + jc*16 + jl2] = s;
    }
}

extern "C" void kernel_launch(void* const* d_in, const int* in_sizes, int n_in,
                              void* d_out, int out_size){
    const float* x    = (const float*)d_in[0];
    const float* W1   = (const float*)d_in[1];
    const float* b1   = (const float*)d_in[2];
    const float* cw   = (const float*)d_in[3];
    const float* cb   = (const float*)d_in[4];
    const float* W2   = (const float*)d_in[5];
    const float* b2   = (const float*)d_in[6];
    const float* Alog = (const float*)d_in[7];
    const float* Dp   = (const float*)d_in[8];
    const float* Wo   = (const float*)d_in[9];
    const float* ob   = (const float*)d_in[10];
    const float* lg   = (const float*)d_in[11];
    const float* lb   = (const float*)d_in[12];
    float* out = (float*)d_out;

    k_dtr  <<<1792,              256>>>(x, W1);
    k_dt   <<<dim3(32,64),       256>>>(W2, b2);
    k_scan <<<dim3(256,4),       256>>>(Alog);
    k_gemm1<<<dim3(17,64),       256>>>(b1);
    k_zc   <<<dim3(33,4),        256>>>(x, W1, b1);
    k_conv <<<dim3(10,64,4),     256>>>(cw, cb);
    k_state<<<dim3(256,4),       256>>>(Alog, Dp);
    k_out  <<<64,                256>>>(Wo, ob, lg, lb, out);
}

// round 14
// speedup vs baseline: 1.5101x; 1.0739x over previous
#include <cuda_runtime.h>
#include <math.h>
#include <stdint.h>

#define B_SZ    4
#define SEQ_L   2048
#define D_MODEL 1024
#define D_INNER 2048
#define D_STATE 16
#define DT_RANK 64
#define IN_DIM  4192
#define NROWS   (B_SZ*SEQ_L)     /* 8192 */
#define NC1     2064             /* x_in(2048) + B(16) columns */
#define COL_OFF 2048
#define WR_LD   2176             /* g_wr row stride (floats), cols >=2064 zero */
#define MY_INT_MAX 0x7fffffff

// ---------------- scratch (static device, no allocs) ----------------
__device__ float g_projT[(size_t)NROWS*NC1];            // x_in | B  (row-major, ld=NC1)
__device__ float g_xr[(size_t)NROWS*D_MODEL];           // tf32-rounded x
__device__ float g_wr[(size_t)D_MODEL*WR_LD];           // tf32-rounded W[:,2048:4112], zero-padded
__device__ float g_dtr[NROWS*DT_RANK];                  // tf32-rounded dtr (only k_dt consumes)
__device__ float g_dt[(size_t)B_SZ*D_INNER*SEQ_L];      // (b,d,t)
__device__ float g_R [(size_t)B_SZ*D_INNER*SEQ_L];      // suffix sums, tail only
__device__ float g_xc[(size_t)B_SZ*D_INNER*SEQ_L];      // silu(conv), tail only
__device__ float g_csum[B_SZ*32*D_INNER];               // per-64-chunk dt sums
__device__ float g_z [B_SZ*D_INNER];
__device__ float g_Cl[B_SZ*D_STATE];
__device__ int   g_tstar[B_SZ*D_INNER];
__device__ int   g_cutraw[B_SZ];
__device__ float g_fm[B_SZ*D_INNER];

__device__ __forceinline__ float softplusf(float x){
    return (x > 15.f) ? x : log1pf(__expf(x));
}

__device__ __forceinline__ float tf32r(float x){
    uint32_t r;
    asm("cvt.rna.tf32.f32 %0, %1;" : "=r"(r) : "f"(x));
    return __uint_as_float(r);
}

__device__ __forceinline__ void mma_tf32(float* c, const uint32_t* a, const uint32_t* b){
    asm volatile(
        "mma.sync.aligned.m16n8k8.row.col.f32.tf32.tf32.f32 "
        "{%0,%1,%2,%3}, {%4,%5,%6,%7}, {%8,%9}, {%0,%1,%2,%3};"
        : "+f"(c[0]), "+f"(c[1]), "+f"(c[2]), "+f"(c[3])
        : "r"(a[0]), "r"(a[1]), "r"(a[2]), "r"(a[3]), "r"(b[0]), "r"(b[1]));
}

__device__ __forceinline__ void cp16(uint32_t dst, const void* src){
    asm volatile("cp.async.cg.shared.global [%0], [%1], 16;" :: "r"(dst), "l"(src));
}
__device__ __forceinline__ void cp_commit(){
    asm volatile("cp.async.commit_group;");
}

// -------- K0: z and C for the LAST timestep only (split-K) --------
__global__ void k_zc(const float* __restrict__ x, const float* __restrict__ W,
                     const float* __restrict__ bias){
    int b = blockIdx.y;
    int tid = threadIdx.x;
    int cl = tid & 63, kq = tid >> 6;
    int c = blockIdx.x*64 + cl;
    __shared__ float xs[1024];
    __shared__ float p[4][64];
    const float* xrow = x + ((size_t)(b*SEQ_L + SEQ_L-1))*D_MODEL;
    for (int i = tid; i < 1024; i += 256) xs[i] = xrow[i];
    __syncthreads();
    float acc = 0.f;
    if (c < 2064){
        int wcol = (c < 2048) ? c : (4112 + (c - 2048));
        const float* wp = W + (size_t)(kq*256)*IN_DIM + wcol;
        #pragma unroll 8
        for (int k = 0; k < 256; k++) acc += xs[kq*256 + k] * wp[(size_t)k*IN_DIM];
    }
    p[kq][cl] = acc;
    __syncthreads();
    if (tid < 64){
        int cc = blockIdx.x*64 + tid;
        if (cc < 2064){
            float s = p[0][tid] + p[1][tid] + p[2][tid] + p[3][tid];
            int wcol = (cc < 2048) ? cc : (4112 + (cc - 2048));
            s += bias[wcol];
            if (cc < 2048) g_z[b*D_INNER + cc] = s;
            else           g_Cl[b*D_STATE + (cc-2048)] = s;
        }
    }
}

// -------- K1: dtr via TF32 MMA (blocks 0..63) + pre-round x / W slab (64..1599) --------
__global__ void k_dtr(const float* __restrict__ x, const float* __restrict__ W,
                      const float* __restrict__ bias){
    int tid = threadIdx.x;
    if (blockIdx.x >= 64){
        int pid = blockIdx.x - 64;
        if (pid < 1024){
            for (size_t i = (size_t)pid*256 + tid; i < 2097152u; i += 262144u){
                float4 v = ((const float4*)x)[i];
                float4 o = make_float4(tf32r(v.x), tf32r(v.y), tf32r(v.z), tf32r(v.w));
                ((float4*)g_xr)[i] = o;
            }
        } else {
            int p2 = pid - 1024;   // 0..511
            for (size_t i = (size_t)p2*256 + tid; i < 557056u; i += 131072u){
                int k  = (int)(i / 544);
                int c4 = (int)(i % 544);
                float4 o = make_float4(0.f,0.f,0.f,0.f);
                if (c4 < 516){
                    float4 v = *(const float4*)(W + (size_t)k*IN_DIM + COL_OFF + c4*4);
                    o = make_float4(tf32r(v.x), tf32r(v.y), tf32r(v.z), tf32r(v.w));
                }
                ((float4*)g_wr)[(size_t)k*544 + c4] = o;
            }
        }
        return;
    }
    // TF32 MMA GEMM: 128 rows x 64 cols, K=1024 (32-k chunks, inline rounding)
    int row0 = blockIdx.x * 128;
    if (blockIdx.x == 0 && tid < B_SZ) g_cutraw[tid] = MY_INT_MAX;

    __shared__ float As[128][36];   // frag bank (4g+t) — conflict-free
    __shared__ float Ws[32][72];    // frag bank (8t+g) — conflict-free
    __shared__ float bs[64];

    int lane = tid & 31;
    int warp = tid >> 5;
    int wr = warp & 3;              // 4 warp-rows * 32
    int wc = warp >> 2;             // 2 warp-cols * 32
    int g = lane >> 2, t = lane & 3;

    if (tid < 64) bs[tid] = bias[4128 + tid];

    float acc[2][4][4];
    #pragma unroll
    for (int mf=0;mf<2;mf++)
        #pragma unroll
        for (int nf=0;nf<4;nf++)
            #pragma unroll
            for (int q=0;q<4;q++) acc[mf][nf][q] = 0.f;

    int aRow = tid >> 1;
    int aK   = (tid & 1) * 16;
    int wK   = tid >> 3;            // 0..31
    int wN   = (tid & 7) * 8;       // 0..56

    for (int kc = 0; kc < 1024; kc += 32){
        __syncthreads();
        #pragma unroll
        for (int jj = 0; jj < 4; jj++){
            float4 v = *(const float4*)(x + (size_t)(row0+aRow)*1024 + kc + aK + jj*4);
            As[aRow][aK+jj*4+0] = tf32r(v.x);
            As[aRow][aK+jj*4+1] = tf32r(v.y);
            As[aRow][aK+jj*4+2] = tf32r(v.z);
            As[aRow][aK+jj*4+3] = tf32r(v.w);
        }
        #pragma unroll
        for (int jj = 0; jj < 2; jj++){
            float4 v = *(const float4*)(W + (size_t)(kc+wK)*IN_DIM + 4128 + wN + jj*4);
            Ws[wK][wN+jj*4+0] = tf32r(v.x);
            Ws[wK][wN+jj*4+1] = tf32r(v.y);
            Ws[wK][wN+jj*4+2] = tf32r(v.z);
            Ws[wK][wN+jj*4+3] = tf32r(v.w);
        }
        __syncthreads();
        #pragma unroll
        for (int kb = 0; kb < 32; kb += 8){
            uint32_t afr[2][4];
            #pragma unroll
            for (int mf = 0; mf < 2; mf++){
                int r = wr*32 + mf*16 + g;
                afr[mf][0] = __float_as_uint(As[r  ][kb+t]);
                afr[mf][1] = __float_as_uint(As[r+8][kb+t]);
                afr[mf][2] = __float_as_uint(As[r  ][kb+t+4]);
                afr[mf][3] = __float_as_uint(As[r+8][kb+t+4]);
            }
            uint32_t bfr[4][2];
            #pragma unroll
            for (int nf = 0; nf < 4; nf++){
                int c = wc*32 + nf*8 + g;
                bfr[nf][0] = __float_as_uint(Ws[kb+t  ][c]);
                bfr[nf][1] = __float_as_uint(Ws[kb+t+4][c]);
            }
            #pragma unroll
            for (int mf=0;mf<2;mf++)
                #pragma unroll
                for (int nf=0;nf<4;nf++)
                    mma_tf32(acc[mf][nf], afr[mf], bfr[nf]);
        }
    }
    // epilogue: +bias (zeros by construction), tf32-round for the tf32 consumer
    #pragma unroll
    for (int mf=0;mf<2;mf++){
        int rA = row0 + wr*32 + mf*16 + g;
        #pragma unroll
        for (int nf=0;nf<4;nf++){
            int c = wc*32 + nf*8 + 2*t;
            float b0 = bs[c], b1 = bs[c+1];
            *(float2*)(g_dtr + (size_t)rA*64 + c) =
                make_float2(tf32r(acc[mf][nf][0] + b0), tf32r(acc[mf][nf][1] + b1));
            *(float2*)(g_dtr + (size_t)(rA+8)*64 + c) =
                make_float2(tf32r(acc[mf][nf][2] + b0), tf32r(acc[mf][nf][3] + b1));
        }
    }
}

// -------- K2: dt via TF32 MMA — 128 t-rows x 64 d-cols per CTA, K=64 --------
__global__ void k_dt(const float* __restrict__ W2, const float* __restrict__ b2){
    int d0 = blockIdx.x*64;
    int row0 = blockIdx.y*128;
    int b = row0 >> 11;
    int t0 = row0 & (SEQ_L-1);

    __shared__ float As[128][36];
    __shared__ float Ws[32][72];
    __shared__ float bs[64];
    __shared__ float sm[4][64];

    int tid = threadIdx.x;
    int lane = tid & 31;
    int warp = tid >> 5;
    int wr = warp & 3;
    int wc = warp >> 2;
    int g = lane >> 2, t = lane & 3;

    if (tid < 64) bs[tid] = b2[d0 + tid];

    float acc[2][4][4];
    #pragma unroll
    for (int mf=0;mf<2;mf++)
        #pragma unroll
        for (int nf=0;nf<4;nf++)
            #pragma unroll
            for (int q=0;q<4;q++) acc[mf][nf][q] = 0.f;

    int aRow = tid >> 1;
    int aK   = (tid & 1) * 16;
    int wK   = tid >> 3;
    int wN   = (tid & 7) * 8;

    #pragma unroll
    for (int kc = 0; kc < 64; kc += 32){
        __syncthreads();
        #pragma unroll
        for (int jj = 0; jj < 4; jj++)
            *(float4*)&As[aRow][aK+jj*4] =
                *(const float4*)(g_dtr + (size_t)(row0+aRow)*64 + kc + aK + jj*4);
        #pragma unroll
        for (int jj = 0; jj < 2; jj++){
            float4 v = *(const float4*)(W2 + (size_t)(kc+wK)*D_INNER + d0 + wN + jj*4);
            Ws[wK][wN+jj*4+0] = tf32r(v.x);
            Ws[wK][wN+jj*4+1] = tf32r(v.y);
            Ws[wK][wN+jj*4+2] = tf32r(v.z);
            Ws[wK][wN+jj*4+3] = tf32r(v.w);
        }
        __syncthreads();
        #pragma unroll
        for (int kb = 0; kb < 32; kb += 8){
            uint32_t afr[2][4];
            #pragma unroll
            for (int mf = 0; mf < 2; mf++){
                int r = wr*32 + mf*16 + g;
                afr[mf][0] = __float_as_uint(As[r  ][kb+t]);
                afr[mf][1] = __float_as_uint(As[r+8][kb+t]);
                afr[mf][2] = __float_as_uint(As[r  ][kb+t+4]);
                afr[mf][3] = __float_as_uint(As[r+8][kb+t+4]);
            }
            uint32_t bfr[4][2];
            #pragma unroll
            for (int nf = 0; nf < 4; nf++){
                int c = wc*32 + nf*8 + g;
                bfr[nf][0] = __float_as_uint(Ws[kb+t  ][c]);
                bfr[nf][1] = __float_as_uint(Ws[kb+t+4][c]);
            }
            #pragma unroll
            for (int mf=0;mf<2;mf++)
                #pragma unroll
                for (int nf=0;nf<4;nf++)
                    mma_tf32(acc[mf][nf], afr[mf], bfr[nf]);
        }
    }

    float sp[2][4][4];
    #pragma unroll
    for (int mf=0;mf<2;mf++){
        int tl = wr*32 + mf*16 + g;
        #pragma unroll
        for (int nf=0;nf<4;nf++){
            int c = wc*32 + nf*8 + 2*t;
            float b0 = bs[c], b1 = bs[c+1];
            sp[mf][nf][0] = softplusf(acc[mf][nf][0] + b0);
            sp[mf][nf][1] = softplusf(acc[mf][nf][1] + b1);
            sp[mf][nf][2] = softplusf(acc[mf][nf][2] + b0);
            sp[mf][nf][3] = softplusf(acc[mf][nf][3] + b1);
            int d = d0 + c;
            g_dt[((size_t)(b*D_INNER + d  ))*SEQ_L + t0 + tl]     = sp[mf][nf][0];
            g_dt[((size_t)(b*D_INNER + d+1))*SEQ_L + t0 + tl]     = sp[mf][nf][1];
            g_dt[((size_t)(b*D_INNER + d  ))*SEQ_L + t0 + tl + 8] = sp[mf][nf][2];
            g_dt[((size_t)(b*D_INNER + d+1))*SEQ_L + t0 + tl + 8] = sp[mf][nf][3];
        }
    }
    #pragma unroll
    for (int nf = 0; nf < 4; nf++){
        float c0 = sp[0][nf][0] + sp[0][nf][2] + sp[1][nf][0] + sp[1][nf][2];
        float c1 = sp[0][nf][1] + sp[0][nf][3] + sp[1][nf][1] + sp[1][nf][3];
        #pragma unroll
        for (int off = 4; off < 32; off <<= 1){
            c0 += __shfl_xor_sync(0xffffffffu, c0, off);
            c1 += __shfl_xor_sync(0xffffffffu, c1, off);
        }
        if (g == 0){
            int c = wc*32 + nf*8 + 2*t;
            sm[wr][c]   = c0;
            sm[wr][c+1] = c1;
        }
    }
    __syncthreads();
    if (tid < 128){
        int half = tid >> 6;
        int col  = tid & 63;
        int chunk = (t0 >> 6) + half;
        g_csum[(b*32 + chunk)*D_INNER + d0 + col] =
            sm[half*2][col] + sm[half*2+1][col];
    }
}

// -------- K3: scan v2 — csum-driven; one warp per (b,d) row --------
__global__ void k_scan(const float* __restrict__ A_log){
    int tid = threadIdx.x;
    int lane = tid & 31;
    int d = blockIdx.x*8 + (tid >> 5);
    int b = blockIdx.y;
    size_t base = ((size_t)(b*D_INNER + d))*SEQ_L;

    float a = (lane < 16) ? -__expf(A_log[d*16 + lane]) : -3.4e38f;
    #pragma unroll
    for (int off = 16; off > 0; off >>= 1)
        a = fmaxf(a, __shfl_xor_sync(0xffffffffu, a, off));
    float Th = -32.f / a;

    float cs = g_csum[(b*32 + lane)*D_INNER + d];
    float S = cs;
    #pragma unroll
    for (int off = 1; off < 32; off <<= 1){
        float v = __shfl_down_sync(0xffffffffu, S, off);
        if (lane + off < 32) S += v;
    }
    float Snext = __shfl_down_sync(0xffffffffu, S, 1);
    if (lane == 31) Snext = 0.f;
    unsigned liveMask = __ballot_sync(0xffffffffu, Snext < Th);
    int cstar = __ffs(liveMask) - 1;

    int tstar = SEQ_L - 1;
    for (int c = cstar; c < 32; c++){
        float Sn = __shfl_sync(0xffffffffu, Snext, c);
        float2 dv = *(const float2*)(g_dt + base + c*64 + lane*2);
        float pair = dv.x + dv.y;
        float P = pair;
        #pragma unroll
        for (int off = 1; off < 32; off <<= 1){
            float v = __shfl_down_sync(0xffffffffu, P, off);
            if (lane + off < 32) P += v;
        }
        float tailp = P - pair;
        float R1 = Sn + tailp;
        float R0 = R1 + dv.y;
        *(float2*)(g_R + base + c*64 + lane*2) = make_float2(R0, R1);
        if (c == cstar){
            unsigned m0 = __ballot_sync(0xffffffffu, R0 < Th);
            unsigned m1 = __ballot_sync(0xffffffffu, R1 < Th);
            int c0 = m0 ? (__ffs(m0)-1)*2     : 0x7fff;
            int c1 = m1 ? (__ffs(m1)-1)*2 + 1 : 0x7fff;
            int tloc = min(c0, c1);
            tstar = c*64 + tloc;
        }
    }
    if (lane == 0){
        int ts = min(tstar, SEQ_L-1);
        g_tstar[b*D_INNER + d] = ts;
        atomicMin(&g_cutraw[b], ts);
    }
}

// -------- K4: row-gated TF32 GEMM v3 — cp.async double-buffered, k-chunk 16 --------
__global__ void k_gemm1(const float* __restrict__ bias){
    int row0 = blockIdx.y*128;
    int b  = row0 / SEQ_L;
    int t0 = row0 % SEQ_L;
    int gate = max(0, g_cutraw[b] - 35);
    if (t0 + 127 < gate) return;
    int n0 = blockIdx.x*128;

    __shared__ float As[2][128][20];
    __shared__ float Ws[2][16][136];

    int tid = threadIdx.x;
    int lane = tid & 31;
    int warp = tid >> 5;
    int wr = warp & 3;
    int wc = warp >> 2;
    int g = lane >> 2, t = lane & 3;

    float acc[2][8][4];
    #pragma unroll
    for (int mf=0;mf<2;mf++)
        #pragma unroll
        for (int nf=0;nf<8;nf++)
            #pragma unroll
            for (int q=0;q<4;q++) acc[mf][nf][q] = 0.f;

    int aRow = tid >> 1;
    int aK   = (tid & 1) * 8;
    int wK   = tid >> 4;
    int wN   = (tid & 15) * 8;

    uint32_t asA = (uint32_t)__cvta_generic_to_shared(&As[0][0][0]);
    uint32_t asW = (uint32_t)__cvta_generic_to_shared(&Ws[0][0][0]);
    uint32_t dA = asA + (uint32_t)((aRow*20 + aK)*4);
    uint32_t dW = asW + (uint32_t)((wK*136 + wN)*4);
    const float* srcA = g_xr + (size_t)(row0 + aRow)*1024 + aK;
    const float* srcW = g_wr + (size_t)wK*WR_LD + n0 + wN;

    cp16(dA,                srcA);
    cp16(dA + 16,           srcA + 4);
    cp16(dW,                srcW);
    cp16(dW + 16,           srcW + 4);
    cp_commit();

    for (int c = 0; c < 64; c++){
        if (c + 1 < 64){
            int nb = (c+1) & 1;
            const float* sA = srcA + (c+1)*16;
            const float* sW = srcW + (size_t)(c+1)*16*WR_LD;
            cp16(dA + nb*10240,      sA);
            cp16(dA + nb*10240 + 16, sA + 4);
            cp16(dW + nb*8704,       sW);
            cp16(dW + nb*8704 + 16,  sW + 4);
            cp_commit();
            asm volatile("cp.async.wait_group 1;");
        } else {
            asm volatile("cp.async.wait_group 0;");
        }
        __syncthreads();
        int buf = c & 1;
        #pragma unroll
        for (int kb = 0; kb < 16; kb += 8){
            uint32_t afr[2][4];
            #pragma unroll
            for (int mf = 0; mf < 2; mf++){
                int r = wr*32 + mf*16 + g;
                afr[mf][0] = __float_as_uint(As[buf][r  ][kb+t]);
                afr[mf][1] = __float_as_uint(As[buf][r+8][kb+t]);
                afr[mf][2] = __float_as_uint(As[buf][r  ][kb+t+4]);
                afr[mf][3] = __float_as_uint(As[buf][r+8][kb+t+4]);
            }
            uint32_t bfr[8][2];
            #pragma unroll
            for (int nf = 0; nf < 8; nf++){
                int cc = wc*64 + nf*8 + g;
                bfr[nf][0] = __float_as_uint(Ws[buf][kb+t  ][cc]);
                bfr[nf][1] = __float_as_uint(Ws[buf][kb+t+4][cc]);
            }
            #pragma unroll
            for (int mf=0;mf<2;mf++)
                #pragma unroll
                for (int nf=0;nf<8;nf++)
                    mma_tf32(acc[mf][nf], afr[mf], bfr[nf]);
        }
        __syncthreads();
    }
    #pragma unroll
    for (int mf=0;mf<2;mf++){
        int rA = row0 + wr*32 + mf*16 + g;
        #pragma unroll
        for (int nf=0;nf<8;nf++){
            int c = n0 + wc*64 + nf*8 + 2*t;
            if (c < NC1){
                float b0 = bias[COL_OFF+c], b1 = bias[COL_OFF+c+1];
                *(float2*)(g_projT + (size_t)rA*NC1 + c) =
                    make_float2(acc[mf][nf][0] + b0, acc[mf][nf][1] + b1);
                *(float2*)(g_projT + (size_t)(rA+8)*NC1 + c) =
                    make_float2(acc[mf][nf][2] + b0, acc[mf][nf][3] + b1);
            }
        }
    }
}

// -------- K5: causal depthwise conv4 + SiLU — compacted grid --------
__global__ void k_conv(const float* __restrict__ cw, const float* __restrict__ cb){
    int d0 = blockIdx.y*32, b = blockIdx.z;
    int lo = g_cutraw[b] & ~31;
    int t0 = SEQ_L - 320 + blockIdx.x*32;
    __shared__ float xs[35][33];
    __shared__ float ws[32][4];
    __shared__ float cbs[32];
    int tid = threadIdx.x;
    for (int i = tid; i < 32*4; i += 256){
        int dd = i >> 2, k = i & 3;
        ws[dd][k] = cw[(d0+dd)*4 + k];
    }
    if (tid < 32) cbs[tid] = cb[d0 + tid];

    int nExtra = 0;
    if (blockIdx.x == 0 && lo < SEQ_L - 320)
        nExtra = (SEQ_L - 320 - lo + 31) >> 5;
    int total = 1 + nExtra;
    for (int it = 0; it < total; it++){
        int tb = (it == 0) ? t0 : lo + (it-1)*32;
        if (it == 0 && t0 + 31 < lo) continue;
        __syncthreads();
        for (int i = tid; i < 35*32; i += 256){
            int tt = i >> 5, dd = i & 31;
            int t = tb - 3 + tt;
            xs[tt][dd] = (t >= 0) ? g_projT[(size_t)(b*SEQ_L + t)*NC1 + d0 + dd] : 0.f;
        }
        __syncthreads();
        for (int o = tid; o < 32*32; o += 256){
            int dd = o >> 5, tl = o & 31;
            float acc = cbs[dd];
            #pragma unroll
            for (int k = 0; k < 4; k++) acc = fmaf(ws[dd][k], xs[tl+k][dd], acc);
            float sg = 1.f / (1.f + __expf(-acc));
            g_xc[((size_t)(b*D_INNER + d0 + dd))*SEQ_L + tb + tl] = acc * sg;
        }
    }
}

// -------- K6: final-state reduction + gates — one warp per (b,d) row --------
__global__ void k_state(const float* __restrict__ A_log, const float* __restrict__ Dp){
    int tid = threadIdx.x;
    int lane = tid & 31;
    int d = blockIdx.x*8 + (tid >> 5);
    int b = blockIdx.y;
    size_t base = ((size_t)(b*D_INNER + d))*SEQ_L;

    float av = (lane < 16) ? -__expf(A_log[d*16 + lane]) : 0.f;
    float cv = (lane < 16) ? g_Cl[b*16 + lane] : 0.f;
    float A_[16], C_[16];
    #pragma unroll
    for (int n = 0; n < 16; n++){
        A_[n] = __shfl_sync(0xffffffffu, av, n);
        C_[n] = __shfl_sync(0xffffffffu, cv, n);
    }

    int ts = g_tstar[b*D_INNER + d];
    float acc[16];
    #pragma unroll
    for (int n = 0; n < 16; n++) acc[n] = 0.f;

    int nIter = (SEQ_L - ts + 31) >> 5;
    for (int it = 0; it < nIter; it++){
        int t = ts + it*32 + lane;
        bool valid = t < SEQ_L;
        float R = 0.f, u = 0.f, Rv = 3.4e38f;
        float Bv[16];
        #pragma unroll
        for (int n = 0; n < 16; n++) Bv[n] = 0.f;
        if (valid){
            R = g_R[base + t];
            u = g_dt[base + t] * g_xc[base + t];
            Rv = R;
            const float4* bp = (const float4*)(g_projT + (size_t)(b*SEQ_L + t)*NC1 + 2048);
            float4 b0 = bp[0], b1 = bp[1], b2 = bp[2], b3 = bp[3];
            Bv[0]=b0.x; Bv[1]=b0.y; Bv[2]=b0.z; Bv[3]=b0.w;
            Bv[4]=b1.x; Bv[5]=b1.y; Bv[6]=b1.z; Bv[7]=b1.w;
            Bv[8]=b2.x; Bv[9]=b2.y; Bv[10]=b2.z; Bv[11]=b2.w;
            Bv[12]=b3.x; Bv[13]=b3.y; Bv[14]=b3.z; Bv[15]=b3.w;
        }
        float Rmin = Rv;
        #pragma unroll
        for (int off = 16; off > 0; off >>= 1)
            Rmin = fminf(Rmin, __shfl_xor_sync(0xffffffffu, Rmin, off));
        #pragma unroll
        for (int n = 0; n < 16; n++){
            if (A_[n]*Rmin > -30.f){
                acc[n] = fmaf(__expf(A_[n]*R)*u, Bv[n], acc[n]);
            }
        }
    }
    #pragma unroll
    for (int n = 0; n < 16; n++){
        #pragma unroll
        for (int off = 16; off > 0; off >>= 1)
            acc[n] += __shfl_xor_sync(0xffffffffu, acc[n], off);
    }
    if (lane == 0){
        float y = 0.f;
        #pragma unroll
        for (int n = 0; n < 16; n++) y = fmaf(acc[n], C_[n], y);
        y += g_xc[base + SEQ_L - 1] * Dp[d];
        float z = g_z[b*D_INNER + d];
        float sg = 1.f / (1.f + __expf(-z));
        y *= z * sg;
        g_fm[b*D_INNER + d] = y;
    }
}

// -------- K7: fused layernorm + out_proj — 64 blocks (16 cols, 16 k-chunks) --------
__global__ void k_out(const float* __restrict__ W, const float* __restrict__ ob,
                      const float* __restrict__ g, const float* __restrict__ beta,
                      float* __restrict__ out){
    int tid = threadIdx.x;
    int jc = blockIdx.x;
    __shared__ float xn[B_SZ][D_INNER];
    __shared__ float r1[256], r2[256];
    __shared__ float pr[16][16][4];
    __shared__ float mu_s[4], rs_s[4];

    for (int b = 0; b < B_SZ; b++){
        float s1 = 0.f, s2 = 0.f;
        for (int i = tid; i < D_INNER; i += 256){
            float v = g_fm[b*D_INNER + i];
            xn[b][i] = v;
            s1 += v; s2 += v*v;
        }
        r1[tid] = s1; r2[tid] = s2;
        __syncthreads();
        for (int off = 128; off > 0; off >>= 1){
            if (tid < off){ r1[tid] += r1[tid+off]; r2[tid] += r2[tid+off]; }
            __syncthreads();
        }
        if (tid == 0){
            float mu = r1[0] / D_INNER;
            float var = r2[0] / D_INNER - mu*mu;
            mu_s[b] = mu;
            rs_s[b] = rsqrtf(var + 1e-5f);
        }
        __syncthreads();
    }
    for (int i = tid; i < D_INNER; i += 256){
        float gg = g[i], bb = beta[i];
        #pragma unroll
        for (int b = 0; b < B_SZ; b++)
            xn[b][i] = (xn[b][i] - mu_s[b]) * rs_s[b] * gg + bb;
    }
    __syncthreads();

    int jl = tid & 15, kq = tid >> 4;
    int j = jc*16 + jl;
    float a0=0.f,a1=0.f,a2=0.f,a3=0.f;
    const float* wp = W + (size_t)(kq*128)*D_MODEL + j;
    #pragma unroll 8
    for (int k = 0; k < 128; k++){
        float w = wp[(size_t)k*D_MODEL];
        int dd = kq*128 + k;
        a0 = fmaf(xn[0][dd], w, a0);
        a1 = fmaf(xn[1][dd], w, a1);
        a2 = fmaf(xn[2][dd], w, a2);
        a3 = fmaf(xn[3][dd], w, a3);
    }
    pr[kq][jl][0]=a0; pr[kq][jl][1]=a1; pr[kq][jl][2]=a2; pr[kq][jl][3]=a3;
    __syncthreads();
    if (tid < 64){
        int jl2 = tid & 15, b = tid >> 4;
        float s = ob[jc*16 + jl2];
        #pragma unroll
        for (int q = 0; q < 16; q++) s += pr[q][jl2][b];
        out[b*D_MODEL + jc*16 + jl2] = s;
    }
}

extern "C" void kernel_launch(void* const* d_in, const int* in_sizes, int n_in,
                              void* d_out, int out_size){
    const float* x    = (const float*)d_in[0];
    const float* W1   = (const float*)d_in[1];
    const float* b1   = (const float*)d_in[2];
    const float* cw   = (const float*)d_in[3];
    const float* cb   = (const float*)d_in[4];
    const float* W2   = (const float*)d_in[5];
    const float* b2   = (const float*)d_in[6];
    const float* Alog = (const float*)d_in[7];
    const float* Dp   = (const float*)d_in[8];
    const float* Wo   = (const float*)d_in[9];
    const float* ob   = (const float*)d_in[10];
    const float* lg   = (const float*)d_in[11];
    const float* lb   = (const float*)d_in[12];
    float* out = (float*)d_out;

    k_dtr  <<<1600,              256>>>(x, W1, b1);
    k_dt   <<<dim3(32,64),       256>>>(W2, b2);
    k_scan <<<dim3(256,4),       256>>>(Alog);
    k_gemm1<<<dim3(17,64),       256>>>(b1);
    k_zc   <<<dim3(33,4),        256>>>(x, W1, b1);
    k_conv <<<dim3(10,64,4),     256>>>(cw, cb);
    k_state<<<dim3(256,4),       256>>>(Alog, Dp);
    k_out  <<<64,                256>>>(Wo, ob, lg, lb, out);
}